// round 15
// baseline (speedup 1.0000x reference)
#include <cuda_runtime.h>
#include <cuda_bf16.h>

// Problem constants: B=4, C=5, H=64, W=64, N=4096
#define BB 4
#define CC 5
#define WW 64
#define HW 4096
#define BSTRIDE 20480      // C*HW
#define NMAX 4096
#define M_TILE 7           // queries per attn block -> ~589 blocks = 2 waves @ 2 CTA/SM
#define LOG2E 1.4426950408889634f
#define KVBLKS 64          // kv blocks in prep (256 threads each)
#define PARTS_PER_B 16     // KVBLKS / BB

// -------- scratch (device globals; no allocation allowed) --------
// interleaved k/v: per (batch, channel, pair) float4 = [k_even, k_odd, v_even, v_odd]
__device__ float4 g_kv[BB * CC * 2048];
__device__ float g_q[NMAX * CC];        // log2(e)-scaled query projections
__device__ int   g_perm[NMAX];
__device__ int   g_off[BB + 1];
__device__ int   g_blkoff[BB + 1];
__device__ float g_pmin[KVBLKS][CC];
__device__ float g_pmax[KVBLKS][CC];
__device__ float g_pnrm[KVBLKS];

__device__ __forceinline__ float ex2f(float x) {
    float r; asm("ex2.approx.f32 %0, %1;" : "=f"(r) : "f"(x)); return r;
}

// ---------------------------------------------------------------
// Kernel 1 (fused), 256 threads/block:
//   blocks [0,64)            : k/v projection (interleaved kv write) + y=x copy + k stats
//   blocks [64,64+qblocks)   : q projection (log2-scaled)
//   last block               : counting sort by batch (MLP-batched loads)
// ---------------------------------------------------------------
__global__ void prep_kernel(const float* __restrict__ x,
                            const float* __restrict__ qw, const float* __restrict__ qb,
                            const float* __restrict__ kw, const float* __restrict__ kb,
                            const float* __restrict__ vw, const float* __restrict__ vb,
                            const int* __restrict__ ib, const int* __restrict__ ih,
                            const int* __restrict__ iw, int n,
                            float* __restrict__ y) {
    int tid = threadIdx.x;
    if (blockIdx.x < KVBLKS) {
        __shared__ float skw[25], skb[5], svw[25], svb[5];
        __shared__ float smin[8][CC], smax[8][CC], snrm[8];
        if (tid < 25) { skw[tid] = kw[tid]; svw[tid] = vw[tid]; }
        if (tid < 5)  { skb[tid] = kb[tid]; svb[tid] = vb[tid]; }
        __syncthreads();

        int t = blockIdx.x * 256 + tid;
        int b = t >> 12;
        int p = t & (HW - 1);
        const float* xb = x + b * BSTRIDE + p;
        float* yb = y + b * BSTRIDE + p;

        float xs[CC];
#pragma unroll
        for (int c = 0; c < CC; c++) { xs[c] = xb[c * HW]; yb[c * HW] = xs[c]; }

        int p2 = p >> 1, half = p & 1;
        float kk[CC]; float nrm = 0.0f;
#pragma unroll
        for (int o = 0; o < CC; o++) {
            float k = skb[o], v = svb[o];
#pragma unroll
            for (int c = 0; c < CC; c++) {
                k = fmaf(skw[o * CC + c], xs[c], k);
                v = fmaf(svw[o * CC + c], xs[c], v);
            }
            float* dst = (float*)&g_kv[(b * CC + o) * 2048 + p2];
            dst[half] = k;
            dst[2 + half] = v;
            kk[o] = k;
            nrm = fmaf(k, k, nrm);
        }

        float mn[CC], mx[CC];
#pragma unroll
        for (int c = 0; c < CC; c++) { mn[c] = kk[c]; mx[c] = kk[c]; }
#pragma unroll
        for (int off = 16; off > 0; off >>= 1) {
#pragma unroll
            for (int c = 0; c < CC; c++) {
                mn[c] = fminf(mn[c], __shfl_xor_sync(0xffffffffu, mn[c], off));
                mx[c] = fmaxf(mx[c], __shfl_xor_sync(0xffffffffu, mx[c], off));
            }
            nrm = fmaxf(nrm, __shfl_xor_sync(0xffffffffu, nrm, off));
        }
        int wid = tid >> 5, lane = tid & 31;
        if (lane == 0) {
#pragma unroll
            for (int c = 0; c < CC; c++) { smin[wid][c] = mn[c]; smax[wid][c] = mx[c]; }
            snrm[wid] = nrm;
        }
        __syncthreads();
        if (tid < CC) {
            float a = smin[0][tid], bx = smax[0][tid];
#pragma unroll
            for (int w = 1; w < 8; w++) { a = fminf(a, smin[w][tid]); bx = fmaxf(bx, smax[w][tid]); }
            g_pmin[blockIdx.x][tid] = a;
            g_pmax[blockIdx.x][tid] = bx;
        }
        if (tid == CC) {
            float a = snrm[0];
#pragma unroll
            for (int w = 1; w < 8; w++) a = fmaxf(a, snrm[w]);
            g_pnrm[blockIdx.x] = a;
        }
    } else if (blockIdx.x < gridDim.x - 1) {
        __shared__ float sw[25], sb[5];
        if (tid < 25) sw[tid] = qw[tid];
        if (tid < 5)  sb[tid] = qb[tid];
        __syncthreads();
        int i = (blockIdx.x - KVBLKS) * 256 + tid;
        if (i >= n) return;
        int b = ib[i];
        int pix = ih[i] * WW + iw[i];
        const float* xb = x + b * BSTRIDE + pix;
        float xs[CC];
#pragma unroll
        for (int c = 0; c < CC; c++) xs[c] = xb[c * HW];
#pragma unroll
        for (int o = 0; o < CC; o++) {
            float q = sb[o];
#pragma unroll
            for (int c = 0; c < CC; c++) q = fmaf(sw[o * CC + c], xs[c], q);
            g_q[i * CC + o] = q * LOG2E;
        }
    } else {
        // counting sort by batch; loads MLP-batched up front.
        // Slot order is numerically irrelevant (per-query compute is
        // slot-independent), so atomic rank order is benign.
        __shared__ int scnt[BB], scur[BB];
        int myb[16];
#pragma unroll
        for (int j = 0; j < 16; j++) {
            int i = tid + j * 256;
            myb[j] = (i < n) ? ib[i] : -1;
        }
        if (tid < BB) scnt[tid] = 0;
        __syncthreads();
        int c0 = 0, c1 = 0, c2 = 0, c3 = 0;
#pragma unroll
        for (int j = 0; j < 16; j++) {
            c0 += (myb[j] == 0); c1 += (myb[j] == 1);
            c2 += (myb[j] == 2); c3 += (myb[j] == 3);
        }
        if (c0) atomicAdd(&scnt[0], c0);
        if (c1) atomicAdd(&scnt[1], c1);
        if (c2) atomicAdd(&scnt[2], c2);
        if (c3) atomicAdd(&scnt[3], c3);
        __syncthreads();
        if (tid == 0) {
            int acc = 0, bacc = 0;
            for (int b = 0; b < BB; b++) {
                int cnt = scnt[b];
                g_off[b] = acc; scur[b] = acc; acc += cnt;
                g_blkoff[b] = bacc; bacc += (cnt + M_TILE - 1) / M_TILE;
            }
            g_off[BB] = acc;
            g_blkoff[BB] = bacc;
        }
        __syncthreads();
#pragma unroll
        for (int j = 0; j < 16; j++) {
            int i = tid + j * 256;
            if (i < n) {
                int pos = atomicAdd(&scur[myb[j]], 1);
                g_perm[pos] = i;
            }
        }
    }
}

// ---------------------------------------------------------------
// Kernel 2: one-pass bounded-softmax attention. M_TILE=7 per 256-thread
// block -> ~589 blocks = exactly 2 waves at 2 CTA/SM. 5x LDG.128
// interleaved k/v. Phase-batched inner body: all 14 energy chains,
// then all 14 ex2 (MUFU latencies overlap), then all accumulates —
// keeps ex2 latency off the critical path.
// Block-uniform true upper bound -> no guard, plain sums.
// ---------------------------------------------------------------
__global__ void __launch_bounds__(256, 2)
attn_kernel(const float* __restrict__ x,
            const int* __restrict__ ih, const int* __restrict__ iw,
            const float* __restrict__ gamma, float* __restrict__ y) {
    int tid = threadIdx.x;

    __shared__ int   s_boff[BB + 1], s_off[BB + 1];
    __shared__ int   s_n[M_TILE];
    __shared__ float s_kmn[CC], s_kmx[CC], s_knrm;
    __shared__ float s_red[M_TILE * 6 * 8];

    if (tid < BB + 1) { s_boff[tid] = g_blkoff[tid]; s_off[tid] = g_off[tid]; }
    __syncthreads();

    int blk = blockIdx.x;
    if (blk >= s_boff[BB]) return;
    int b = 0;
    while (blk >= s_boff[b + 1]) b++;
    int base = s_off[b] + (blk - s_boff[b]) * M_TILE;
    int end = s_off[b + 1];
    int mcnt = min(M_TILE, end - base);

    if (tid < M_TILE) s_n[tid] = (tid < mcnt) ? g_perm[base + tid] : -1;
    // finalize per-batch k stats from PARTS_PER_B partials (cheap, per block)
    if (tid >= 32 && tid < 32 + CC) {
        int c = tid - 32;
        float a = 3.0e38f;
#pragma unroll
        for (int k = 0; k < PARTS_PER_B; k++) a = fminf(a, g_pmin[b * PARTS_PER_B + k][c]);
        s_kmn[c] = a;
    } else if (tid >= 64 && tid < 64 + CC) {
        int c = tid - 64;
        float a = -3.0e38f;
#pragma unroll
        for (int k = 0; k < PARTS_PER_B; k++) a = fmaxf(a, g_pmax[b * PARTS_PER_B + k][c]);
        s_kmx[c] = a;
    } else if (tid == 96) {
        float a = 0.0f;
#pragma unroll
        for (int k = 0; k < PARTS_PER_B; k++) a = fmaxf(a, g_pnrm[b * PARTS_PER_B + k]);
        s_knrm = sqrtf(a);
    }
    __syncthreads();

    float q[M_TILE][CC];
#pragma unroll
    for (int m = 0; m < M_TILE; m++) {
        int nq = s_n[m];
#pragma unroll
        for (int c = 0; c < CC; c++)
            q[m][c] = (nq >= 0) ? __ldg(&g_q[nq * CC + c]) : 0.0f;
    }

    // nlmax[m] = 32 - min(separable, Cauchy) upper bound (block-uniform)
    float nlmax[M_TILE];
    {
        float knrm = s_knrm;
#pragma unroll
        for (int m = 0; m < M_TILE; m++) {
            float sep = 0.0f, qq = 0.0f;
#pragma unroll
            for (int c = 0; c < CC; c++) {
                sep += fmaxf(q[m][c] * s_kmx[c], q[m][c] * s_kmn[c]);
                qq = fmaf(q[m][c], q[m][c], qq);
            }
            float cau = sqrtf(qq) * knrm;
            nlmax[m] = 32.0f - fminf(sep, cau);
        }
    }

    const float4* kv = g_kv + b * CC * 2048;

    float ssum[M_TILE];
    float oacc[M_TILE][CC];
#pragma unroll
    for (int m = 0; m < M_TILE; m++) {
        ssum[m] = 0.0f;
#pragma unroll
        for (int c = 0; c < CC; c++) oacc[m][c] = 0.0f;
    }

    // sweep over 2048 pairs (8 iters of 256); phase-batched body
#pragma unroll 4
    for (int it = 0; it < 8; it++) {
        int p2 = tid + it * 256;
        float4 b0 = kv[p2];
        float4 b1 = kv[2048 + p2];
        float4 b2 = kv[2 * 2048 + p2];
        float4 b3 = kv[3 * 2048 + p2];
        float4 b4 = kv[4 * 2048 + p2];

        // phase 1: all 14 energy chains (independent)
        float ex[M_TILE], ey[M_TILE];
#pragma unroll
        for (int m = 0; m < M_TILE; m++) {
            float e = fmaf(q[m][0], b0.x, nlmax[m]);
            e = fmaf(q[m][1], b1.x, e);
            e = fmaf(q[m][2], b2.x, e);
            e = fmaf(q[m][3], b3.x, e);
            e = fmaf(q[m][4], b4.x, e);
            ex[m] = e;
            float f = fmaf(q[m][0], b0.y, nlmax[m]);
            f = fmaf(q[m][1], b1.y, f);
            f = fmaf(q[m][2], b2.y, f);
            f = fmaf(q[m][3], b3.y, f);
            f = fmaf(q[m][4], b4.y, f);
            ey[m] = f;
        }
        // phase 2: all 14 MUFU exps back-to-back (latencies overlap)
        float wx[M_TILE], wy[M_TILE];
#pragma unroll
        for (int m = 0; m < M_TILE; m++) {
            wx[m] = ex2f(ex[m]);
            wy[m] = ex2f(ey[m]);
        }
        // phase 3: accumulates (independent given w's)
#pragma unroll
        for (int m = 0; m < M_TILE; m++) {
            ssum[m] += wx[m] + wy[m];
            oacc[m][0] = fmaf(wx[m], b0.z, fmaf(wy[m], b0.w, oacc[m][0]));
            oacc[m][1] = fmaf(wx[m], b1.z, fmaf(wy[m], b1.w, oacc[m][1]));
            oacc[m][2] = fmaf(wx[m], b2.z, fmaf(wy[m], b2.w, oacc[m][2]));
            oacc[m][3] = fmaf(wx[m], b3.z, fmaf(wy[m], b3.w, oacc[m][3]));
            oacc[m][4] = fmaf(wx[m], b4.z, fmaf(wy[m], b4.w, oacc[m][4]));
        }
    }

    int wid = tid >> 5, lane = tid & 31;

    // ---- sum reduction (bound uniform -> plain sums) ----
#pragma unroll
    for (int m = 0; m < M_TILE; m++) {
#pragma unroll
        for (int off = 16; off > 0; off >>= 1)
            ssum[m] += __shfl_xor_sync(0xffffffffu, ssum[m], off);
#pragma unroll
        for (int c = 0; c < CC; c++) {
#pragma unroll
            for (int off = 16; off > 0; off >>= 1)
                oacc[m][c] += __shfl_xor_sync(0xffffffffu, oacc[m][c], off);
        }
    }
    if (lane == 0) {
#pragma unroll
        for (int m = 0; m < M_TILE; m++) {
            s_red[(m * 6 + 0) * 8 + wid] = ssum[m];
#pragma unroll
            for (int c = 0; c < CC; c++)
                s_red[(m * 6 + 1 + c) * 8 + wid] = oacc[m][c];
        }
    }
    __syncthreads();

    if (tid < mcnt) {
        int m = tid;
        float s = 0.0f;
#pragma unroll
        for (int w = 0; w < 8; w++) s += s_red[(m * 6) * 8 + w];
        float inv = 1.0f / s;
        float g = gamma[0];
        int nq = s_n[m];
        int pix = ih[nq] * WW + iw[nq];
#pragma unroll
        for (int c = 0; c < CC; c++) {
            float oc = 0.0f;
#pragma unroll
            for (int w = 0; w < 8; w++) oc += s_red[(m * 6 + 1 + c) * 8 + w];
            int idx = b * BSTRIDE + c * HW + pix;
            y[idx] = fmaf(g, oc * inv, x[idx]);
        }
    }
}

// ---------------------------------------------------------------
// launch
// ---------------------------------------------------------------
extern "C" void kernel_launch(void* const* d_in, const int* in_sizes, int n_in,
                              void* d_out, int out_size) {
    const float* x     = (const float*)d_in[0];
    const float* qw    = (const float*)d_in[2];
    const float* qb    = (const float*)d_in[3];
    const float* kw    = (const float*)d_in[4];
    const float* kb    = (const float*)d_in[5];
    const float* vw    = (const float*)d_in[6];
    const float* vb    = (const float*)d_in[7];
    const float* gamma = (const float*)d_in[8];
    const int*   ib    = (const int*)d_in[9];
    const int*   ih    = (const int*)d_in[10];
    const int*   iw    = (const int*)d_in[11];
    float* y = (float*)d_out;

    int n = in_sizes[9];
    int qblocks = (n + 255) / 256;

    prep_kernel<<<KVBLKS + qblocks + 1, 256>>>(x, qw, qb, kw, kb, vw, vb, ib, ih, iw, n, y);

    int maxblk = (n + M_TILE - 1) / M_TILE + BB - 1;   // upper bound on working blocks
    attn_kernel<<<maxblk, 256>>>(x, ih, iw, gamma, y);
}

// round 16
// speedup vs baseline: 1.2913x; 1.2913x over previous
#include <cuda_runtime.h>
#include <cuda_bf16.h>

// Problem constants: B=4, C=5, H=64, W=64, N=4096
#define BB 4
#define CC 5
#define WW 64
#define HW 4096
#define BSTRIDE 20480      // C*HW
#define NMAX 4096
#define M_TILE 7           // queries per attn block -> ~589 blocks = 2 waves @ 2 CTA/SM
#define LOG2E 1.4426950408889634f
#define KVBLKS 64          // kv blocks in prep (256 threads each)
#define PARTS_PER_B 16     // KVBLKS / BB

// -------- scratch (device globals; no allocation allowed) --------
// interleaved k/v: per (batch, channel, pair) float4 = [k_even, k_odd, v_even, v_odd]
__device__ float4 g_kv[BB * CC * 2048];
__device__ float g_q[NMAX * CC];        // log2(e)-scaled query projections
__device__ int   g_perm[NMAX];
__device__ int   g_off[BB + 1];
__device__ int   g_blkoff[BB + 1];
__device__ float g_pmin[KVBLKS][CC];
__device__ float g_pmax[KVBLKS][CC];
__device__ float g_pnrm[KVBLKS];

__device__ __forceinline__ float ex2f(float x) {
    float r; asm("ex2.approx.f32 %0, %1;" : "=f"(r) : "f"(x)); return r;
}

// ---------------------------------------------------------------
// Kernel 1 (fused), 256 threads/block:
//   blocks [0,64)            : k/v projection (interleaved kv write) + y=x copy + k stats
//   blocks [64,64+qblocks)   : q projection (log2-scaled)
//   last block               : ballot-based atomic-free counting sort by batch
// ---------------------------------------------------------------
__global__ void prep_kernel(const float* __restrict__ x,
                            const float* __restrict__ qw, const float* __restrict__ qb,
                            const float* __restrict__ kw, const float* __restrict__ kb,
                            const float* __restrict__ vw, const float* __restrict__ vb,
                            const int* __restrict__ ib, const int* __restrict__ ih,
                            const int* __restrict__ iw, int n,
                            float* __restrict__ y) {
    int tid = threadIdx.x;
    if (blockIdx.x < KVBLKS) {
        __shared__ float skw[25], skb[5], svw[25], svb[5];
        __shared__ float smin[8][CC], smax[8][CC], snrm[8];
        if (tid < 25) { skw[tid] = kw[tid]; svw[tid] = vw[tid]; }
        if (tid < 5)  { skb[tid] = kb[tid]; svb[tid] = vb[tid]; }
        __syncthreads();

        int t = blockIdx.x * 256 + tid;
        int b = t >> 12;
        int p = t & (HW - 1);
        const float* xb = x + b * BSTRIDE + p;
        float* yb = y + b * BSTRIDE + p;

        float xs[CC];
#pragma unroll
        for (int c = 0; c < CC; c++) { xs[c] = xb[c * HW]; yb[c * HW] = xs[c]; }

        int p2 = p >> 1, half = p & 1;
        float kk[CC]; float nrm = 0.0f;
#pragma unroll
        for (int o = 0; o < CC; o++) {
            float k = skb[o], v = svb[o];
#pragma unroll
            for (int c = 0; c < CC; c++) {
                k = fmaf(skw[o * CC + c], xs[c], k);
                v = fmaf(svw[o * CC + c], xs[c], v);
            }
            float* dst = (float*)&g_kv[(b * CC + o) * 2048 + p2];
            dst[half] = k;
            dst[2 + half] = v;
            kk[o] = k;
            nrm = fmaf(k, k, nrm);
        }

        float mn[CC], mx[CC];
#pragma unroll
        for (int c = 0; c < CC; c++) { mn[c] = kk[c]; mx[c] = kk[c]; }
#pragma unroll
        for (int off = 16; off > 0; off >>= 1) {
#pragma unroll
            for (int c = 0; c < CC; c++) {
                mn[c] = fminf(mn[c], __shfl_xor_sync(0xffffffffu, mn[c], off));
                mx[c] = fmaxf(mx[c], __shfl_xor_sync(0xffffffffu, mx[c], off));
            }
            nrm = fmaxf(nrm, __shfl_xor_sync(0xffffffffu, nrm, off));
        }
        int wid = tid >> 5, lane = tid & 31;
        if (lane == 0) {
#pragma unroll
            for (int c = 0; c < CC; c++) { smin[wid][c] = mn[c]; smax[wid][c] = mx[c]; }
            snrm[wid] = nrm;
        }
        __syncthreads();
        if (tid < CC) {
            float a = smin[0][tid], bx = smax[0][tid];
#pragma unroll
            for (int w = 1; w < 8; w++) { a = fminf(a, smin[w][tid]); bx = fmaxf(bx, smax[w][tid]); }
            g_pmin[blockIdx.x][tid] = a;
            g_pmax[blockIdx.x][tid] = bx;
        }
        if (tid == CC) {
            float a = snrm[0];
#pragma unroll
            for (int w = 1; w < 8; w++) a = fmaxf(a, snrm[w]);
            g_pnrm[blockIdx.x] = a;
        }
    } else if (blockIdx.x < gridDim.x - 1) {
        __shared__ float sw[25], sb[5];
        if (tid < 25) sw[tid] = qw[tid];
        if (tid < 5)  sb[tid] = qb[tid];
        __syncthreads();
        int i = (blockIdx.x - KVBLKS) * 256 + tid;
        if (i >= n) return;
        int b = ib[i];
        int pix = ih[i] * WW + iw[i];
        const float* xb = x + b * BSTRIDE + pix;
        float xs[CC];
#pragma unroll
        for (int c = 0; c < CC; c++) xs[c] = xb[c * HW];
#pragma unroll
        for (int o = 0; o < CC; o++) {
            float q = sb[o];
#pragma unroll
            for (int c = 0; c < CC; c++) q = fmaf(sw[o * CC + c], xs[c], q);
            g_q[i * CC + o] = q * LOG2E;
        }
    } else {
        // ------- ballot-based atomic-free counting sort by batch -------
        // 8 warps; warp w owns index range [w*16*32, ...) in 16 lane-strided
        // steps. Deterministic, zero atomics.
        __shared__ int s_wcnt[8][BB];     // per-warp per-batch counts
        __shared__ int s_wbase[8][BB];    // per-warp per-batch scatter bases
        int wid = tid >> 5, lane = tid & 31;

        int myb[16];
#pragma unroll
        for (int j = 0; j < 16; j++) {
            int i = wid * 512 + j * 32 + lane;
            myb[j] = (i < n) ? ib[i] : -1;
        }

        // phase 1: warp counts via ballot+popc
        int cnt[BB] = {0, 0, 0, 0};
#pragma unroll
        for (int j = 0; j < 16; j++) {
#pragma unroll
            for (int b = 0; b < BB; b++) {
                unsigned mask = __ballot_sync(0xffffffffu, myb[j] == b);
                cnt[b] += __popc(mask);
            }
        }
        if (lane == 0) {
#pragma unroll
            for (int b = 0; b < BB; b++) s_wcnt[wid][b] = cnt[b];
        }
        __syncthreads();

        // phase 2: serial scan of 32 values (one thread) -> offsets + bases
        if (tid == 0) {
            int tot[BB];
#pragma unroll
            for (int b = 0; b < BB; b++) {
                int s = 0;
                for (int w = 0; w < 8; w++) s += s_wcnt[w][b];
                tot[b] = s;
            }
            int acc = 0, bacc = 0;
            for (int b = 0; b < BB; b++) {
                g_off[b] = acc;
                g_blkoff[b] = bacc;
                int run = acc;
                for (int w = 0; w < 8; w++) { s_wbase[w][b] = run; run += s_wcnt[w][b]; }
                acc += tot[b];
                bacc += (tot[b] + M_TILE - 1) / M_TILE;
            }
            g_off[BB] = acc;
            g_blkoff[BB] = bacc;
        }
        __syncthreads();

        // phase 3: scatter via ballot prefix (atomic-free)
        int base[BB];
#pragma unroll
        for (int b = 0; b < BB; b++) base[b] = s_wbase[wid][b];
        unsigned lmask = (1u << lane) - 1u;
#pragma unroll
        for (int j = 0; j < 16; j++) {
            int i = wid * 512 + j * 32 + lane;
#pragma unroll
            for (int b = 0; b < BB; b++) {
                unsigned mask = __ballot_sync(0xffffffffu, myb[j] == b);
                if (myb[j] == b) g_perm[base[b] + __popc(mask & lmask)] = i;
                base[b] += __popc(mask);
            }
        }
    }
}

// ---------------------------------------------------------------
// Kernel 2: one-pass bounded-softmax attention (exact R12 best config).
// M_TILE=7 per 256-thread block -> ~589 blocks = exactly 2 waves at
// 2 CTA/SM. 5x LDG.128 interleaved k/v, per-m serial body, unroll 2.
// Block-uniform true upper bound -> no guard, plain sums.
// ---------------------------------------------------------------
__global__ void __launch_bounds__(256, 2)
attn_kernel(const float* __restrict__ x,
            const int* __restrict__ ih, const int* __restrict__ iw,
            const float* __restrict__ gamma, float* __restrict__ y) {
    int tid = threadIdx.x;

    __shared__ int   s_boff[BB + 1], s_off[BB + 1];
    __shared__ int   s_n[M_TILE];
    __shared__ float s_kmn[CC], s_kmx[CC], s_knrm;
    __shared__ float s_red[M_TILE * 6 * 8];

    if (tid < BB + 1) { s_boff[tid] = g_blkoff[tid]; s_off[tid] = g_off[tid]; }
    __syncthreads();

    int blk = blockIdx.x;
    if (blk >= s_boff[BB]) return;
    int b = 0;
    while (blk >= s_boff[b + 1]) b++;
    int base = s_off[b] + (blk - s_boff[b]) * M_TILE;
    int end = s_off[b + 1];
    int mcnt = min(M_TILE, end - base);

    if (tid < M_TILE) s_n[tid] = (tid < mcnt) ? g_perm[base + tid] : -1;
    // finalize per-batch k stats from PARTS_PER_B partials (cheap, per block)
    if (tid >= 32 && tid < 32 + CC) {
        int c = tid - 32;
        float a = 3.0e38f;
#pragma unroll
        for (int k = 0; k < PARTS_PER_B; k++) a = fminf(a, g_pmin[b * PARTS_PER_B + k][c]);
        s_kmn[c] = a;
    } else if (tid >= 64 && tid < 64 + CC) {
        int c = tid - 64;
        float a = -3.0e38f;
#pragma unroll
        for (int k = 0; k < PARTS_PER_B; k++) a = fmaxf(a, g_pmax[b * PARTS_PER_B + k][c]);
        s_kmx[c] = a;
    } else if (tid == 96) {
        float a = 0.0f;
#pragma unroll
        for (int k = 0; k < PARTS_PER_B; k++) a = fmaxf(a, g_pnrm[b * PARTS_PER_B + k]);
        s_knrm = sqrtf(a);
    }
    __syncthreads();

    float q[M_TILE][CC];
#pragma unroll
    for (int m = 0; m < M_TILE; m++) {
        int nq = s_n[m];
#pragma unroll
        for (int c = 0; c < CC; c++)
            q[m][c] = (nq >= 0) ? __ldg(&g_q[nq * CC + c]) : 0.0f;
    }

    // nlmax[m] = 32 - min(separable, Cauchy) upper bound (block-uniform)
    float nlmax[M_TILE];
    {
        float knrm = s_knrm;
#pragma unroll
        for (int m = 0; m < M_TILE; m++) {
            float sep = 0.0f, qq = 0.0f;
#pragma unroll
            for (int c = 0; c < CC; c++) {
                sep += fmaxf(q[m][c] * s_kmx[c], q[m][c] * s_kmn[c]);
                qq = fmaf(q[m][c], q[m][c], qq);
            }
            float cau = sqrtf(qq) * knrm;
            nlmax[m] = 32.0f - fminf(sep, cau);
        }
    }

    const float4* kv = g_kv + b * CC * 2048;

    float ssum[M_TILE];
    float oacc[M_TILE][CC];
#pragma unroll
    for (int m = 0; m < M_TILE; m++) {
        ssum[m] = 0.0f;
#pragma unroll
        for (int c = 0; c < CC; c++) oacc[m][c] = 0.0f;
    }

    // sweep over 2048 pairs (8 iters of 256), unroll 2 for load/compute overlap
#pragma unroll 2
    for (int it = 0; it < 8; it++) {
        int p2 = tid + it * 256;
        float4 b0 = kv[p2];
        float4 b1 = kv[2048 + p2];
        float4 b2 = kv[2 * 2048 + p2];
        float4 b3 = kv[3 * 2048 + p2];
        float4 b4 = kv[4 * 2048 + p2];
#pragma unroll
        for (int m = 0; m < M_TILE; m++) {
            float ex = fmaf(q[m][0], b0.x, nlmax[m]);
            ex = fmaf(q[m][1], b1.x, ex);
            ex = fmaf(q[m][2], b2.x, ex);
            ex = fmaf(q[m][3], b3.x, ex);
            ex = fmaf(q[m][4], b4.x, ex);
            float ey = fmaf(q[m][0], b0.y, nlmax[m]);
            ey = fmaf(q[m][1], b1.y, ey);
            ey = fmaf(q[m][2], b2.y, ey);
            ey = fmaf(q[m][3], b3.y, ey);
            ey = fmaf(q[m][4], b4.y, ey);
            float wx = ex2f(ex);
            float wy = ex2f(ey);
            ssum[m] += wx + wy;
            oacc[m][0] = fmaf(wx, b0.z, fmaf(wy, b0.w, oacc[m][0]));
            oacc[m][1] = fmaf(wx, b1.z, fmaf(wy, b1.w, oacc[m][1]));
            oacc[m][2] = fmaf(wx, b2.z, fmaf(wy, b2.w, oacc[m][2]));
            oacc[m][3] = fmaf(wx, b3.z, fmaf(wy, b3.w, oacc[m][3]));
            oacc[m][4] = fmaf(wx, b4.z, fmaf(wy, b4.w, oacc[m][4]));
        }
    }

    int wid = tid >> 5, lane = tid & 31;

    // ---- sum reduction (bound uniform -> plain sums) ----
#pragma unroll
    for (int m = 0; m < M_TILE; m++) {
#pragma unroll
        for (int off = 16; off > 0; off >>= 1)
            ssum[m] += __shfl_xor_sync(0xffffffffu, ssum[m], off);
#pragma unroll
        for (int c = 0; c < CC; c++) {
#pragma unroll
            for (int off = 16; off > 0; off >>= 1)
                oacc[m][c] += __shfl_xor_sync(0xffffffffu, oacc[m][c], off);
        }
    }
    if (lane == 0) {
#pragma unroll
        for (int m = 0; m < M_TILE; m++) {
            s_red[(m * 6 + 0) * 8 + wid] = ssum[m];
#pragma unroll
            for (int c = 0; c < CC; c++)
                s_red[(m * 6 + 1 + c) * 8 + wid] = oacc[m][c];
        }
    }
    __syncthreads();

    if (tid < mcnt) {
        int m = tid;
        float s = 0.0f;
#pragma unroll
        for (int w = 0; w < 8; w++) s += s_red[(m * 6) * 8 + w];
        float inv = 1.0f / s;
        float g = gamma[0];
        int nq = s_n[m];
        int pix = ih[nq] * WW + iw[nq];
#pragma unroll
        for (int c = 0; c < CC; c++) {
            float oc = 0.0f;
#pragma unroll
            for (int w = 0; w < 8; w++) oc += s_red[(m * 6 + 1 + c) * 8 + w];
            int idx = b * BSTRIDE + c * HW + pix;
            y[idx] = fmaf(g, oc * inv, x[idx]);
        }
    }
}

// ---------------------------------------------------------------
// launch
// ---------------------------------------------------------------
extern "C" void kernel_launch(void* const* d_in, const int* in_sizes, int n_in,
                              void* d_out, int out_size) {
    const float* x     = (const float*)d_in[0];
    const float* qw    = (const float*)d_in[2];
    const float* qb    = (const float*)d_in[3];
    const float* kw    = (const float*)d_in[4];
    const float* kb    = (const float*)d_in[5];
    const float* vw    = (const float*)d_in[6];
    const float* vb    = (const float*)d_in[7];
    const float* gamma = (const float*)d_in[8];
    const int*   ib    = (const int*)d_in[9];
    const int*   ih    = (const int*)d_in[10];
    const int*   iw    = (const int*)d_in[11];
    float* y = (float*)d_out;

    int n = in_sizes[9];
    int qblocks = (n + 255) / 256;

    prep_kernel<<<KVBLKS + qblocks + 1, 256>>>(x, qw, qb, kw, kb, vw, vb, ib, ih, iw, n, y);

    int maxblk = (n + M_TILE - 1) / M_TILE + BB - 1;   // upper bound on working blocks
    attn_kernel<<<maxblk, 256>>>(x, ih, iw, gamma, y);
}

// round 17
// speedup vs baseline: 1.4952x; 1.1580x over previous
#include <cuda_runtime.h>
#include <cuda_bf16.h>

// Problem constants: B=4, C=5, H=64, W=64, N=4096
#define BB 4
#define CC 5
#define WW 64
#define HW 4096
#define BSTRIDE 20480      // C*HW
#define NMAX 4096
#define M_TILE 7
#define LOG2E 1.4426950408889634f
#define KVBLKS 64
#define PARTS_PER_B 16     // KVBLKS / BB
#define NBLK 296           // persistent grid: 2 CTAs/SM x 148 SMs (<= capacity on 152 too)

// -------- scratch (device globals; no allocation allowed) --------
__device__ float4 g_kv[BB * CC * 2048];  // [k_even,k_odd,v_even,v_odd] per (b,c,pair)
__device__ float g_q[NMAX * CC];
__device__ int   g_perm[NMAX];
__device__ int   g_off[BB + 1];
__device__ int   g_blkoff[BB + 1];
__device__ float g_pmin[KVBLKS][CC];
__device__ float g_pmax[KVBLKS][CC];
__device__ float g_pnrm[KVBLKS];
__device__ unsigned g_bar;               // monotone grid-barrier counter (replay-safe)

__device__ __forceinline__ float ex2f(float x) {
    float r; asm("ex2.approx.f32 %0, %1;" : "=f"(r) : "f"(x)); return r;
}

// ---------------------------------------------------------------
// Single persistent kernel. Phase A (role-split): kv+stats / q / sort.
// Grid barrier. Phase B: attn tiles t = blk, blk+NBLK (R12 mainloop).
// ---------------------------------------------------------------
__global__ void __launch_bounds__(256, 2)
fused_kernel(const float* __restrict__ x,
             const float* __restrict__ qw, const float* __restrict__ qb,
             const float* __restrict__ kw, const float* __restrict__ kb,
             const float* __restrict__ vw, const float* __restrict__ vb,
             const int* __restrict__ ib, const int* __restrict__ ih,
             const int* __restrict__ iw, int n,
             const float* __restrict__ gamma, float* __restrict__ y) {
    int tid = threadIdx.x;
    int blk = blockIdx.x;

    __shared__ float s_smem[64];           // phase-A scratch (aliased views below)
    __shared__ int   s_boff[BB + 1], s_off[BB + 1];
    __shared__ int   s_n[M_TILE];
    __shared__ float s_kmn[CC], s_kmx[CC], s_knrm;
    __shared__ float s_red[M_TILE * 6 * 8];
    __shared__ int   s_scnt[BB], s_scur[BB];

    // ================= PHASE A =================
    if (blk < KVBLKS) {
        // ---- kv projection + y=x copy + per-block k stats ----
        __shared__ float skw[25], skb[5], svw[25], svb[5];
        float (*smin)[CC] = (float(*)[CC])s_smem;          // 8*5
        float (*smax)[CC] = (float(*)[CC])(s_smem + 40);   // hmm need 40+40+8 <= 88 > 64
        // use s_red as stat scratch instead (336 floats available)
        smin = (float(*)[CC])s_red;
        smax = (float(*)[CC])(s_red + 40);
        float* snrm = s_red + 80;

        if (tid < 25) { skw[tid] = kw[tid]; svw[tid] = vw[tid]; }
        if (tid < 5)  { skb[tid] = kb[tid]; svb[tid] = vb[tid]; }
        __syncthreads();

        int t = blk * 256 + tid;
        int b = t >> 12;
        int p = t & (HW - 1);
        const float* xb = x + b * BSTRIDE + p;
        float* yb = y + b * BSTRIDE + p;

        float xs[CC];
#pragma unroll
        for (int c = 0; c < CC; c++) { xs[c] = xb[c * HW]; yb[c * HW] = xs[c]; }

        int p2 = p >> 1, half = p & 1;
        float kk[CC]; float nrm = 0.0f;
#pragma unroll
        for (int o = 0; o < CC; o++) {
            float k = skb[o], v = svb[o];
#pragma unroll
            for (int c = 0; c < CC; c++) {
                k = fmaf(skw[o * CC + c], xs[c], k);
                v = fmaf(svw[o * CC + c], xs[c], v);
            }
            float* dst = (float*)&g_kv[(b * CC + o) * 2048 + p2];
            dst[half] = k;
            dst[2 + half] = v;
            kk[o] = k;
            nrm = fmaf(k, k, nrm);
        }

        float mn[CC], mx[CC];
#pragma unroll
        for (int c = 0; c < CC; c++) { mn[c] = kk[c]; mx[c] = kk[c]; }
#pragma unroll
        for (int off = 16; off > 0; off >>= 1) {
#pragma unroll
            for (int c = 0; c < CC; c++) {
                mn[c] = fminf(mn[c], __shfl_xor_sync(0xffffffffu, mn[c], off));
                mx[c] = fmaxf(mx[c], __shfl_xor_sync(0xffffffffu, mx[c], off));
            }
            nrm = fmaxf(nrm, __shfl_xor_sync(0xffffffffu, nrm, off));
        }
        int wid = tid >> 5, lane = tid & 31;
        if (lane == 0) {
#pragma unroll
            for (int c = 0; c < CC; c++) { smin[wid][c] = mn[c]; smax[wid][c] = mx[c]; }
            snrm[wid] = nrm;
        }
        __syncthreads();
        if (tid < CC) {
            float a = smin[0][tid], bx = smax[0][tid];
#pragma unroll
            for (int w = 1; w < 8; w++) { a = fminf(a, smin[w][tid]); bx = fmaxf(bx, smax[w][tid]); }
            g_pmin[blk][tid] = a;
            g_pmax[blk][tid] = bx;
        }
        if (tid == CC) {
            float a = snrm[0];
#pragma unroll
            for (int w = 1; w < 8; w++) a = fmaxf(a, snrm[w]);
            g_pnrm[blk] = a;
        }
    } else if (blk < KVBLKS + 16) {
        // ---- q projection ----
        __shared__ float sw[25], sb[5];
        if (tid < 25) sw[tid] = qw[tid];
        if (tid < 5)  sb[tid] = qb[tid];
        __syncthreads();
        int i = (blk - KVBLKS) * 256 + tid;
        if (i < n) {
            int b = ib[i];
            int pix = ih[i] * WW + iw[i];
            const float* xb = x + b * BSTRIDE + pix;
            float xs[CC];
#pragma unroll
            for (int c = 0; c < CC; c++) xs[c] = xb[c * HW];
#pragma unroll
            for (int o = 0; o < CC; o++) {
                float q = sb[o];
#pragma unroll
                for (int c = 0; c < CC; c++) q = fmaf(sw[o * CC + c], xs[c], q);
                g_q[i * CC + o] = q * LOG2E;
            }
        }
    } else if (blk == KVBLKS + 16) {
        // ---- counting sort by batch (MLP-batched loads, smem atomics) ----
        int myb[16];
#pragma unroll
        for (int j = 0; j < 16; j++) {
            int i = tid + j * 256;
            myb[j] = (i < n) ? ib[i] : -1;
        }
        if (tid < BB) s_scnt[tid] = 0;
        __syncthreads();
        int c0 = 0, c1 = 0, c2 = 0, c3 = 0;
#pragma unroll
        for (int j = 0; j < 16; j++) {
            c0 += (myb[j] == 0); c1 += (myb[j] == 1);
            c2 += (myb[j] == 2); c3 += (myb[j] == 3);
        }
        if (c0) atomicAdd(&s_scnt[0], c0);
        if (c1) atomicAdd(&s_scnt[1], c1);
        if (c2) atomicAdd(&s_scnt[2], c2);
        if (c3) atomicAdd(&s_scnt[3], c3);
        __syncthreads();
        if (tid == 0) {
            int acc = 0, bacc = 0;
            for (int b = 0; b < BB; b++) {
                int cnt = s_scnt[b];
                g_off[b] = acc; s_scur[b] = acc; acc += cnt;
                g_blkoff[b] = bacc; bacc += (cnt + M_TILE - 1) / M_TILE;
            }
            g_off[BB] = acc;
            g_blkoff[BB] = bacc;
        }
        __syncthreads();
#pragma unroll
        for (int j = 0; j < 16; j++) {
            int i = tid + j * 256;
            if (i < n) {
                int pos = atomicAdd(&s_scur[myb[j]], 1);
                g_perm[pos] = i;
            }
        }
    }
    // blocks 81..295: no phase-A work

    // ================= GRID BARRIER =================
    __threadfence();                     // publish phase-A writes
    __syncthreads();                     // whole block done before arrival
    if (tid == 0) {
        unsigned val = atomicAdd(&g_bar, 1u) + 1u;
        unsigned target = ((val - 1u) / NBLK + 1u) * NBLK;   // replay-safe monotone
        unsigned cur;
        do {
            asm volatile("ld.acquire.gpu.u32 %0, [%1];" : "=r"(cur) : "l"(&g_bar));
        } while (cur < target);
    }
    __syncthreads();

    // ================= PHASE B: attention tiles =================
    if (tid < BB + 1) { s_boff[tid] = g_blkoff[tid]; s_off[tid] = g_off[tid]; }
    __syncthreads();
    int totblk = s_boff[BB];

    for (int t = blk; t < totblk; t += NBLK) {
        __syncthreads();    // protect smem reuse across tiles

        int b = 0;
        while (t >= s_boff[b + 1]) b++;
        int base = s_off[b] + (t - s_boff[b]) * M_TILE;
        int end = s_off[b + 1];
        int mcnt = min(M_TILE, end - base);

        if (tid < M_TILE) s_n[tid] = (tid < mcnt) ? g_perm[base + tid] : -1;
        if (tid >= 32 && tid < 32 + CC) {
            int c = tid - 32;
            float a = 3.0e38f;
#pragma unroll
            for (int k = 0; k < PARTS_PER_B; k++) a = fminf(a, g_pmin[b * PARTS_PER_B + k][c]);
            s_kmn[c] = a;
        } else if (tid >= 64 && tid < 64 + CC) {
            int c = tid - 64;
            float a = -3.0e38f;
#pragma unroll
            for (int k = 0; k < PARTS_PER_B; k++) a = fmaxf(a, g_pmax[b * PARTS_PER_B + k][c]);
            s_kmx[c] = a;
        } else if (tid == 96) {
            float a = 0.0f;
#pragma unroll
            for (int k = 0; k < PARTS_PER_B; k++) a = fmaxf(a, g_pnrm[b * PARTS_PER_B + k]);
            s_knrm = sqrtf(a);
        }
        __syncthreads();

        float q[M_TILE][CC];
#pragma unroll
        for (int m = 0; m < M_TILE; m++) {
            int nq = s_n[m];
#pragma unroll
            for (int c = 0; c < CC; c++)
                q[m][c] = (nq >= 0) ? __ldg(&g_q[nq * CC + c]) : 0.0f;
        }

        float nlmax[M_TILE];
        {
            float knrm = s_knrm;
#pragma unroll
            for (int m = 0; m < M_TILE; m++) {
                float sep = 0.0f, qq = 0.0f;
#pragma unroll
                for (int c = 0; c < CC; c++) {
                    sep += fmaxf(q[m][c] * s_kmx[c], q[m][c] * s_kmn[c]);
                    qq = fmaf(q[m][c], q[m][c], qq);
                }
                float cau = sqrtf(qq) * knrm;
                nlmax[m] = 32.0f - fminf(sep, cau);
            }
        }

        const float4* kv = g_kv + b * CC * 2048;

        float ssum[M_TILE];
        float oacc[M_TILE][CC];
#pragma unroll
        for (int m = 0; m < M_TILE; m++) {
            ssum[m] = 0.0f;
#pragma unroll
            for (int c = 0; c < CC; c++) oacc[m][c] = 0.0f;
        }

#pragma unroll 2
        for (int it = 0; it < 8; it++) {
            int p2 = tid + it * 256;
            float4 b0 = kv[p2];
            float4 b1 = kv[2048 + p2];
            float4 b2 = kv[2 * 2048 + p2];
            float4 b3 = kv[3 * 2048 + p2];
            float4 b4 = kv[4 * 2048 + p2];
#pragma unroll
            for (int m = 0; m < M_TILE; m++) {
                float ex = fmaf(q[m][0], b0.x, nlmax[m]);
                ex = fmaf(q[m][1], b1.x, ex);
                ex = fmaf(q[m][2], b2.x, ex);
                ex = fmaf(q[m][3], b3.x, ex);
                ex = fmaf(q[m][4], b4.x, ex);
                float ey = fmaf(q[m][0], b0.y, nlmax[m]);
                ey = fmaf(q[m][1], b1.y, ey);
                ey = fmaf(q[m][2], b2.y, ey);
                ey = fmaf(q[m][3], b3.y, ey);
                ey = fmaf(q[m][4], b4.y, ey);
                float wx = ex2f(ex);
                float wy = ex2f(ey);
                ssum[m] += wx + wy;
                oacc[m][0] = fmaf(wx, b0.z, fmaf(wy, b0.w, oacc[m][0]));
                oacc[m][1] = fmaf(wx, b1.z, fmaf(wy, b1.w, oacc[m][1]));
                oacc[m][2] = fmaf(wx, b2.z, fmaf(wy, b2.w, oacc[m][2]));
                oacc[m][3] = fmaf(wx, b3.z, fmaf(wy, b3.w, oacc[m][3]));
                oacc[m][4] = fmaf(wx, b4.z, fmaf(wy, b4.w, oacc[m][4]));
            }
        }

        int wid = tid >> 5, lane = tid & 31;
#pragma unroll
        for (int m = 0; m < M_TILE; m++) {
#pragma unroll
            for (int off = 16; off > 0; off >>= 1)
                ssum[m] += __shfl_xor_sync(0xffffffffu, ssum[m], off);
#pragma unroll
            for (int c = 0; c < CC; c++) {
#pragma unroll
                for (int off = 16; off > 0; off >>= 1)
                    oacc[m][c] += __shfl_xor_sync(0xffffffffu, oacc[m][c], off);
            }
        }
        if (lane == 0) {
#pragma unroll
            for (int m = 0; m < M_TILE; m++) {
                s_red[(m * 6 + 0) * 8 + wid] = ssum[m];
#pragma unroll
                for (int c = 0; c < CC; c++)
                    s_red[(m * 6 + 1 + c) * 8 + wid] = oacc[m][c];
            }
        }
        __syncthreads();

        if (tid < mcnt) {
            int m = tid;
            float s = 0.0f;
#pragma unroll
            for (int w = 0; w < 8; w++) s += s_red[(m * 6) * 8 + w];
            float inv = 1.0f / s;
            float g = gamma[0];
            int nq = s_n[m];
            int pix = ih[nq] * WW + iw[nq];
#pragma unroll
            for (int c = 0; c < CC; c++) {
                float oc = 0.0f;
#pragma unroll
                for (int w = 0; w < 8; w++) oc += s_red[(m * 6 + 1 + c) * 8 + w];
                int idx = b * BSTRIDE + c * HW + pix;
                y[idx] = fmaf(g, oc * inv, x[idx]);
            }
        }
    }
}

// ---------------------------------------------------------------
// launch: one persistent kernel
// ---------------------------------------------------------------
extern "C" void kernel_launch(void* const* d_in, const int* in_sizes, int n_in,
                              void* d_out, int out_size) {
    const float* x     = (const float*)d_in[0];
    const float* qw    = (const float*)d_in[2];
    const float* qb    = (const float*)d_in[3];
    const float* kw    = (const float*)d_in[4];
    const float* kb    = (const float*)d_in[5];
    const float* vw    = (const float*)d_in[6];
    const float* vb    = (const float*)d_in[7];
    const float* gamma = (const float*)d_in[8];
    const int*   ib    = (const int*)d_in[9];
    const int*   ih    = (const int*)d_in[10];
    const int*   iw    = (const int*)d_in[11];
    float* y = (float*)d_out;

    int n = in_sizes[9];

    fused_kernel<<<NBLK, 256>>>(x, qw, qb, kw, kb, vw, vb, ib, ih, iw, n, gamma, y);
}